// round 15
// baseline (speedup 1.0000x reference)
#include <cuda_runtime.h>
#include <cstdint>

#define H       30
#define BATCHN  16384
#define SEQ     784
#define NC      10
#define THREADS 128
#define TCH     28          // 784 = 28 * 28
#define NDP     15          // dim pairs

typedef unsigned long long ull;

// Packed weight table, 128B per output dim d:
//   floats [0..29]  = W_hh[d][0..29]
//   float  [30]     = W_ih[d]
//   float  [31]     = b_mod[d]
__device__   __align__(16) float g_wpack[H * 32];
__constant__ __align__(16) float cW[H * 32];

__device__ __forceinline__ ull ffma2(ull a, ull b, ull c) {
    ull d; asm("fma.rn.f32x2 %0, %1, %2, %3;" : "=l"(d) : "l"(a), "l"(b), "l"(c)); return d;
}
__device__ __forceinline__ ull pack2(float lo, float hi) {
    ull d; asm("mov.b64 %0, {%1, %2};" : "=l"(d) : "f"(lo), "f"(hi)); return d;
}
__device__ __forceinline__ void unpack2(ull v, float& lo, float& hi) {
    asm("mov.b64 {%0, %1}, %2;" : "=f"(lo), "=f"(hi) : "l"(v));
}
__device__ __forceinline__ float modrelu(float z, float b) {
    float m = fmaxf(fabsf(z) + b, 0.0f);
    unsigned r = __float_as_uint(m) | (__float_as_uint(z) & 0x80000000u);
    return __uint_as_float(r);
}

__global__ void repack_kernel(const float* __restrict__ W_hh,
                              const float* __restrict__ W_ih,
                              const float* __restrict__ b_mod) {
    for (int i = threadIdx.x; i < H * 32; i += blockDim.x) {
        const int d = i >> 5, k = i & 31;
        float v;
        if (k < H)       v = W_hh[d * H + k];
        else if (k == H) v = W_ih[d];
        else             v = b_mod[d];
        g_wpack[i] = v;
    }
}

__global__ __launch_bounds__(THREADS)
void rnn_modrelu_kernel(const float* __restrict__ inputs,   // [B, SEQ]
                        const float* __restrict__ W_lin,    // [NC, H]
                        const float* __restrict__ b_lin,    // [NC]
                        float* __restrict__ out)            // [B, NC]
{
    __shared__ __align__(16) float xs[TCH * THREADS];   // 14336 B

    const int tid = threadIdx.x;
    const int b   = blockIdx.x * THREADS + tid;
    const int b0  = blockIdx.x * THREADS;

    // h packed in registers: hp[q] = (h_2q, h_2q+1)
    ull hp[NDP];
#pragma unroll
    for (int q = 0; q < NDP; q++) hp[q] = 0ull;

    const ulonglong2* wtab = (const ulonglong2*)cW;   // 8 u2 per dim row

    for (int ch = 0; ch < TCH; ch++) {
        // ---- stage 28 steps of x for all 128 rows ----
        for (int idx = tid; idx < TCH * THREADS; idx += THREADS) {
            const int r = idx / TCH;
            const int i = idx - r * TCH;
            xs[i * THREADS + r] = inputs[(size_t)(b0 + r) * SEQ + ch * TCH + i];
        }
        __syncthreads();

#pragma unroll 1
        for (int i = 0; i < TCH; i++) {
            const float x = xs[i * THREADS + tid];

            ull hnext[NDP];
#pragma unroll 3
            for (int p = 0; p < NDP; p++) {
                const ulonglong2* r0 = wtab + (2 * p) * 8;
                const ulonglong2* r1 = wtab + (2 * p + 1) * 8;

                // two 15-deep partial-product chains (dims 2p, 2p+1)
                ull a = 0ull, c = 0ull;
#pragma unroll
                for (int q = 0; q < 7; q++) {
                    const ulonglong2 u0 = r0[q];    // LDC.128 (warp-uniform)
                    const ulonglong2 u1 = r1[q];
                    a = ffma2(u0.x, hp[2 * q],     a);
                    c = ffma2(u1.x, hp[2 * q],     c);
                    a = ffma2(u0.y, hp[2 * q + 1], a);
                    c = ffma2(u1.y, hp[2 * q + 1], c);
                }
                const ulonglong2 t0 = r0[7];   // (.x = k-pair 14, .y = (wih, b))
                const ulonglong2 t1 = r1[7];
                a = ffma2(t0.x, hp[14], a);
                c = ffma2(t1.x, hp[14], c);

                float al, ah, cl, chh;
                unpack2(a, al, ah);
                unpack2(c, cl, chh);
                float w0, bb0, w1, bb1;
                unpack2(t0.y, w0, bb0);
                unpack2(t1.y, w1, bb1);

                const float z0 = fmaf(x, w0, al + ah);
                const float z1 = fmaf(x, w1, cl + chh);
                hnext[p] = pack2(modrelu(z0, bb0), modrelu(z1, bb1));
            }
#pragma unroll
            for (int q = 0; q < NDP; q++) hp[q] = hnext[q];
        }
        __syncthreads();   // xs reuse barrier
    }

    // ---- final linear ----
    float h[H];
#pragma unroll
    for (int q = 0; q < NDP; q++) unpack2(hp[q], h[2 * q], h[2 * q + 1]);
#pragma unroll
    for (int c = 0; c < NC; c++) {
        float s = b_lin[c];
#pragma unroll
        for (int k = 0; k < H; k++)
            s = fmaf(W_lin[c * H + k], h[k], s);
        out[(size_t)b * NC + c] = s;
    }
}

extern "C" void kernel_launch(void* const* d_in, const int* in_sizes, int n_in,
                              void* d_out, int out_size) {
    const float* inputs = (const float*)d_in[0];
    const float* W_ih   = (const float*)d_in[1];
    const float* W_hh   = (const float*)d_in[2];
    const float* b_mod  = (const float*)d_in[3];
    const float* W_lin  = (const float*)d_in[4];
    const float* b_lin  = (const float*)d_in[5];
    float* out = (float*)d_out;

    // 1) pack weights into device scratch
    repack_kernel<<<1, 128>>>(W_hh, W_ih, b_mod);

    // 2) scratch -> constant bank (async D2D, graph-capturable)
    void* sp = nullptr;
    cudaGetSymbolAddress(&sp, g_wpack);
    cudaMemcpyToSymbolAsync(cW, sp, sizeof(float) * H * 32, 0,
                            cudaMemcpyDeviceToDevice, 0);

    // 3) main RNN kernel
    rnn_modrelu_kernel<<<BATCHN / THREADS, THREADS>>>(inputs, W_lin, b_lin, out);
}

// round 16
// speedup vs baseline: 6.9104x; 6.9104x over previous
#include <cuda_runtime.h>
#include <cstdint>

#define H       30
#define HP      32
#define BATCHN  16384
#define SEQ     784
#define NC      10

#define WARPS    4          // warps per block; each warp: 2 batch elements
#define EPW      2
#define THREADS  128
#define TCHUNK   112        // 784 = 7 * 112
#define NCHUNK   7

typedef unsigned long long ull;

__device__ __forceinline__ ull ffma2(ull a, ull b, ull c) {
    ull d; asm("fma.rn.f32x2 %0, %1, %2, %3;" : "=l"(d) : "l"(a), "l"(b), "l"(c)); return d;
}
__device__ __forceinline__ ull fadd2(ull a, ull b) {
    ull d; asm("add.rn.f32x2 %0, %1, %2;" : "=l"(d) : "l"(a), "l"(b)); return d;
}
__device__ __forceinline__ ull pack2(float lo, float hi) {
    ull d; asm("mov.b64 %0, {%1, %2};" : "=l"(d) : "f"(lo), "f"(hi)); return d;
}
__device__ __forceinline__ void unpack2(ull v, float& lo, float& hi) {
    asm("mov.b64 {%0, %1}, %2;" : "=f"(lo), "=f"(hi) : "l"(v));
}
__device__ __forceinline__ ull shflx2(ull v, int m) {
    float lo, hi; unpack2(v, lo, hi);
    lo = __shfl_xor_sync(0xFFFFFFFFu, lo, m);
    hi = __shfl_xor_sync(0xFFFFFFFFu, hi, m);
    return pack2(lo, hi);
}
__device__ __forceinline__ float modrelu(float z, float b) {
    float m = fmaxf(fabsf(z) + b, 0.0f);
    unsigned r = __float_as_uint(m) | (__float_as_uint(z) & 0x80000000u);
    return __uint_as_float(r);
}

__global__ __launch_bounds__(THREADS)
void rnn_modrelu_kernel(const float* __restrict__ inputs,   // [B, SEQ]
                        const float* __restrict__ W_ih,     // [H, 1]
                        const float* __restrict__ W_hh,     // [H, H]
                        const float* __restrict__ b_mod,    // [H]
                        const float* __restrict__ W_lin,    // [NC, H]
                        const float* __restrict__ b_lin,    // [NC]
                        float* __restrict__ out)            // [B, NC]
{
    // Warp-PRIVATE x staging: xs[warp][step][elem] -> no block barriers in loop.
    __shared__ __align__(16) float xs[WARPS][TCHUNK][EPW];
    // Per-warp double-buffered hidden state: h_sh[warp][buf][elem][dim].
    __shared__ __align__(128) float h_sh[WARPS][2][EPW][HP];

    const int tid  = threadIdx.x;
    const int w    = tid >> 5;
    const int lane = tid & 31;
    const int j    = lane & 15;     // dim base
    const int s    = lane >> 4;     // k-half: k in [16s, 16s+16)
    const int d    = j + 16 * s;    // dim this lane FINALIZES
    const bool dok = (d < H);

    const int b0 = (blockIdx.x * WARPS + w) * EPW;   // first batch element

    // Per-lane weights: rows j and j+16, k-half s only, packed along k.
    ull wp0[8], wp1[8];
    const int ks = 16 * s;
    const int r1 = j + 16;
#pragma unroll
    for (int i = 0; i < 8; i++) {
        int k0 = ks + 2 * i, k1 = k0 + 1;
        float a0 = (k0 < H) ? W_hh[j * H + k0] : 0.0f;
        float a1 = (k1 < H) ? W_hh[j * H + k1] : 0.0f;
        wp0[i] = pack2(a0, a1);
        float c0 = (r1 < H && k0 < H) ? W_hh[r1 * H + k0] : 0.0f;
        float c1 = (r1 < H && k1 < H) ? W_hh[r1 * H + k1] : 0.0f;
        wp1[i] = pack2(c0, c1);
    }
    const float wihd = dok ? W_ih[d]  : 0.0f;
    const float bd   = dok ? b_mod[d] : 0.0f;

    // init hidden state buffers to zero
#pragma unroll
    for (int e = 0; e < EPW; e++) {
        h_sh[w][0][e][lane] = 0.0f;
        h_sh[w][1][e][lane] = 0.0f;
    }
    __syncwarp();

    for (int ch = 0; ch < NCHUNK; ch++) {
        // ---- warp-local staging of this warp's 2 rows (no __syncthreads) ----
#pragma unroll
        for (int e = 0; e < EPW; e++) {
            const float* rp = inputs + (size_t)(b0 + e) * SEQ + ch * TCHUNK;
#pragma unroll
            for (int t = 0; t < 4; t++) {
                const int i = lane + 32 * t;
                if (i < TCHUNK) xs[w][i][e] = rp[i];
            }
        }
        __syncwarp();

#pragma unroll 2
        for (int i = 0; i < TCHUNK; i++) {
            const int rb = i & 1;

            float xA, xB;
            unpack2(*(const ull*)&xs[w][i][0], xA, xB);

            const ulonglong2* pa = (const ulonglong2*)&h_sh[w][rb][0][ks];
            const ulonglong2* pb = (const ulonglong2*)&h_sh[w][rb][1][ks];
            ulonglong2 a0 = pa[0], a1 = pa[1], a2 = pa[2], a3 = pa[3];
            ulonglong2 c0 = pb[0], c1 = pb[1], c2 = pb[2], c3 = pb[3];

            // 4 independent chains: (P0,P1) for elems A and B
            ull A0 = ffma2(wp0[0], a0.x, 0ull);
            ull A1 = ffma2(wp1[0], a0.x, 0ull);
            ull C0 = ffma2(wp0[0], c0.x, 0ull);
            ull C1 = ffma2(wp1[0], c0.x, 0ull);
            A0 = ffma2(wp0[1], a0.y, A0);  A1 = ffma2(wp1[1], a0.y, A1);
            C0 = ffma2(wp0[1], c0.y, C0);  C1 = ffma2(wp1[1], c0.y, C1);
            A0 = ffma2(wp0[2], a1.x, A0);  A1 = ffma2(wp1[2], a1.x, A1);
            C0 = ffma2(wp0[2], c1.x, C0);  C1 = ffma2(wp1[2], c1.x, C1);
            A0 = ffma2(wp0[3], a1.y, A0);  A1 = ffma2(wp1[3], a1.y, A1);
            C0 = ffma2(wp0[3], c1.y, C0);  C1 = ffma2(wp1[3], c1.y, C1);
            A0 = ffma2(wp0[4], a2.x, A0);  A1 = ffma2(wp1[4], a2.x, A1);
            C0 = ffma2(wp0[4], c2.x, C0);  C1 = ffma2(wp1[4], c2.x, C1);
            A0 = ffma2(wp0[5], a2.y, A0);  A1 = ffma2(wp1[5], a2.y, A1);
            C0 = ffma2(wp0[5], c2.y, C0);  C1 = ffma2(wp1[5], c2.y, C1);
            A0 = ffma2(wp0[6], a3.x, A0);  A1 = ffma2(wp1[6], a3.x, A1);
            C0 = ffma2(wp0[6], c3.x, C0);  C1 = ffma2(wp1[6], c3.x, C1);
            A0 = ffma2(wp0[7], a3.y, A0);  A1 = ffma2(wp1[7], a3.y, A1);
            C0 = ffma2(wp0[7], c3.y, C0);  C1 = ffma2(wp1[7], c3.y, C1);

            // exchange with the other k-half (lane ^ 16)
            const ull sendA = (s == 0) ? A1 : A0;
            const ull keepA = (s == 0) ? A0 : A1;
            const ull sendC = (s == 0) ? C1 : C0;
            const ull keepC = (s == 0) ? C0 : C1;
            const ull ZA = fadd2(keepA, shflx2(sendA, 16));
            const ull ZC = fadd2(keepC, shflx2(sendC, 16));

            float zal, zah, zcl, zch;
            unpack2(ZA, zal, zah);
            unpack2(ZC, zcl, zch);
            const float zA = fmaf(xA, wihd, zal + zah);
            const float zC = fmaf(xB, wihd, zcl + zch);
            // inactive dims (d=30,31): weights/bias zero -> h stays 0
            h_sh[w][1 - rb][0][d] = modrelu(zA, bd);
            h_sh[w][1 - rb][1][d] = modrelu(zC, bd);
            __syncwarp();
        }
    }

    // Final state in buffer 0 (even chunk length).
    if (lane < NC) {
        const int c = lane;
        float wl[H];
#pragma unroll
        for (int k = 0; k < H; k++) wl[k] = W_lin[c * H + k];
        const float bl = b_lin[c];
#pragma unroll
        for (int e = 0; e < EPW; e++) {
            const float* hE = &h_sh[w][0][e][0];
            float sE = bl;
#pragma unroll
            for (int k = 0; k < H; k++) sE = fmaf(wl[k], hE[k], sE);
            out[(size_t)(b0 + e) * NC + c] = sE;
        }
    }
}

extern "C" void kernel_launch(void* const* d_in, const int* in_sizes, int n_in,
                              void* d_out, int out_size) {
    const float* inputs = (const float*)d_in[0];
    const float* W_ih   = (const float*)d_in[1];
    const float* W_hh   = (const float*)d_in[2];
    const float* b_mod  = (const float*)d_in[3];
    const float* W_lin  = (const float*)d_in[4];
    const float* b_lin  = (const float*)d_in[5];
    float* out = (float*)d_out;

    const int nblocks = BATCHN / (EPW * WARPS);   // 2048
    rnn_modrelu_kernel<<<nblocks, THREADS>>>(inputs, W_ih, W_hh, b_mod,
                                             W_lin, b_lin, out);
}

// round 17
// speedup vs baseline: 7.5756x; 1.0963x over previous
#include <cuda_runtime.h>
#include <cstdint>

#define H       30
#define HP      32
#define BATCHN  16384
#define SEQ     784
#define NC      10

#define WARPS    4          // warps per block; each warp: 2 batch elements
#define EPW      2
#define THREADS  128
#define TCHUNK   112        // 784 = 7 * 112
#define NCHUNK   7

typedef unsigned long long ull;

__device__ __forceinline__ ull ffma2(ull a, ull b, ull c) {
    ull d; asm("fma.rn.f32x2 %0, %1, %2, %3;" : "=l"(d) : "l"(a), "l"(b), "l"(c)); return d;
}
__device__ __forceinline__ ull fadd2(ull a, ull b) {
    ull d; asm("add.rn.f32x2 %0, %1, %2;" : "=l"(d) : "l"(a), "l"(b)); return d;
}
__device__ __forceinline__ ull pack2(float lo, float hi) {
    ull d; asm("mov.b64 %0, {%1, %2};" : "=l"(d) : "f"(lo), "f"(hi)); return d;
}
__device__ __forceinline__ void unpack2(ull v, float& lo, float& hi) {
    asm("mov.b64 {%0, %1}, %2;" : "=f"(lo), "=f"(hi) : "l"(v));
}
__device__ __forceinline__ ull shflx2(ull v, int m) {
    float lo, hi; unpack2(v, lo, hi);
    lo = __shfl_xor_sync(0xFFFFFFFFu, lo, m);
    hi = __shfl_xor_sync(0xFFFFFFFFu, hi, m);
    return pack2(lo, hi);
}
__device__ __forceinline__ float modrelu(float z, float b) {
    float m = fmaxf(fabsf(z) + b, 0.0f);
    unsigned r = __float_as_uint(m) | (__float_as_uint(z) & 0x80000000u);
    return __uint_as_float(r);
}

// One recurrence step. hrd/hwr: [EPW][HP] float blocks (read/write buffers).
// Chains: M = partial for MY dim (d) over my k-half; O = partial for partner's
// dim (d^16) over my k-half. Exchange O halves via shfl.
__device__ __forceinline__ void rnn_step(
    float xA, float xB,
    const float* __restrict__ hrd, float* __restrict__ hwr,
    const ull* __restrict__ wpM, const ull* __restrict__ wpO,
    int ks, int d, float wihd, float bd)
{
    const ulonglong2* pa = (const ulonglong2*)(hrd + ks);
    const ulonglong2* pb = (const ulonglong2*)(hrd + HP + ks);
    ulonglong2 a0 = pa[0], a1 = pa[1], a2 = pa[2], a3 = pa[3];
    ulonglong2 c0 = pb[0], c1 = pb[1], c2 = pb[2], c3 = pb[3];

    ull AM = ffma2(wpM[0], a0.x, 0ull);
    ull AO = ffma2(wpO[0], a0.x, 0ull);
    ull BM = ffma2(wpM[0], c0.x, 0ull);
    ull BO = ffma2(wpO[0], c0.x, 0ull);
    AM = ffma2(wpM[1], a0.y, AM);  AO = ffma2(wpO[1], a0.y, AO);
    BM = ffma2(wpM[1], c0.y, BM);  BO = ffma2(wpO[1], c0.y, BO);
    AM = ffma2(wpM[2], a1.x, AM);  AO = ffma2(wpO[2], a1.x, AO);
    BM = ffma2(wpM[2], c1.x, BM);  BO = ffma2(wpO[2], c1.x, BO);
    AM = ffma2(wpM[3], a1.y, AM);  AO = ffma2(wpO[3], a1.y, AO);
    BM = ffma2(wpM[3], c1.y, BM);  BO = ffma2(wpO[3], c1.y, BO);
    AM = ffma2(wpM[4], a2.x, AM);  AO = ffma2(wpO[4], a2.x, AO);
    BM = ffma2(wpM[4], c2.x, BM);  BO = ffma2(wpO[4], c2.x, BO);
    AM = ffma2(wpM[5], a2.y, AM);  AO = ffma2(wpO[5], a2.y, AO);
    BM = ffma2(wpM[5], c2.y, BM);  BO = ffma2(wpO[5], c2.y, BO);
    AM = ffma2(wpM[6], a3.x, AM);  AO = ffma2(wpO[6], a3.x, AO);
    BM = ffma2(wpM[6], c3.x, BM);  BO = ffma2(wpO[6], c3.x, BO);
    AM = ffma2(wpM[7], a3.y, AM);  AO = ffma2(wpO[7], a3.y, AO);
    BM = ffma2(wpM[7], c3.y, BM);  BO = ffma2(wpO[7], c3.y, BO);

    const ull ZA = fadd2(AM, shflx2(AO, 16));
    const ull ZB = fadd2(BM, shflx2(BO, 16));

    float zal, zah, zbl, zbh;
    unpack2(ZA, zal, zah);
    unpack2(ZB, zbl, zbh);
    const float zA = fmaf(xA, wihd, zal + zah);
    const float zB = fmaf(xB, wihd, zbl + zbh);
    hwr[d]      = modrelu(zA, bd);   // inactive dims: weights/bias zero -> 0
    hwr[HP + d] = modrelu(zB, bd);
    __syncwarp();
}

__global__ __launch_bounds__(THREADS)
void rnn_modrelu_kernel(const float* __restrict__ inputs,   // [B, SEQ]
                        const float* __restrict__ W_ih,     // [H, 1]
                        const float* __restrict__ W_hh,     // [H, H]
                        const float* __restrict__ b_mod,    // [H]
                        const float* __restrict__ W_lin,    // [NC, H]
                        const float* __restrict__ b_lin,    // [NC]
                        float* __restrict__ out)            // [B, NC]
{
    // Warp-private x staging, 2 steps packed per float4:
    // xs4[w][i2] = (xA_{2i2}, xB_{2i2}, xA_{2i2+1}, xB_{2i2+1})
    __shared__ __align__(16) float4 xs4[WARPS][TCHUNK / 2];
    // Per-warp double-buffered hidden state: [warp][buf][elem][dim].
    __shared__ __align__(128) float h_sh[WARPS][2][EPW][HP];

    const int tid  = threadIdx.x;
    const int w    = tid >> 5;
    const int lane = tid & 31;
    const int j    = lane & 15;
    const int s    = lane >> 4;          // k-half
    const int d    = j + 16 * s;         // dim this lane finalizes
    const int dO   = d ^ 16;             // partner's dim
    const bool dok = (d < H);

    const int b0 = (blockIdx.x * WARPS + w) * EPW;

    // Weights: MINE = row d, OTHER = row d^16, over my k-half, packed along k.
    ull wpM[8], wpO[8];
    const int ks = 16 * s;
#pragma unroll
    for (int i = 0; i < 8; i++) {
        int k0 = ks + 2 * i, k1 = k0 + 1;
        float m0 = (d  < H && k0 < H) ? W_hh[d  * H + k0] : 0.0f;
        float m1 = (d  < H && k1 < H) ? W_hh[d  * H + k1] : 0.0f;
        float o0 = (dO < H && k0 < H) ? W_hh[dO * H + k0] : 0.0f;
        float o1 = (dO < H && k1 < H) ? W_hh[dO * H + k1] : 0.0f;
        wpM[i] = pack2(m0, m1);
        wpO[i] = pack2(o0, o1);
    }
    const float wihd = dok ? W_ih[d]  : 0.0f;
    const float bd   = dok ? b_mod[d] : 0.0f;

#pragma unroll
    for (int e = 0; e < EPW; e++) {
        h_sh[w][0][e][lane] = 0.0f;
        h_sh[w][1][e][lane] = 0.0f;
    }
    __syncwarp();

    const float* hb0 = &h_sh[w][0][0][0];
    float*       hb1 = &h_sh[w][1][0][0];

    for (int ch = 0; ch < NCHUNK; ch++) {
        // ---- warp-local staging (coalesced reads, packed writes) ----
#pragma unroll
        for (int e = 0; e < EPW; e++) {
            const float* rp = inputs + (size_t)(b0 + e) * SEQ + ch * TCHUNK;
            float* xw = (float*)&xs4[w][0];
#pragma unroll
            for (int t = 0; t < 4; t++) {
                const int i = lane + 32 * t;
                if (i < TCHUNK)
                    xw[(i >> 1) * 4 + ((i & 1) << 1) + e] = rp[i];
            }
        }
        __syncwarp();

#pragma unroll 1
        for (int i2 = 0; i2 < TCHUNK / 2; i2++) {
            const float4 xq = xs4[w][i2];
            // even step: read buf0, write buf1
            rnn_step(xq.x, xq.y, hb0, hb1, wpM, wpO, ks, d, wihd, bd);
            // odd step: read buf1, write buf0
            rnn_step(xq.z, xq.w, hb1, (float*)hb0, wpM, wpO, ks, d, wihd, bd);
        }
    }

    // Final state in buffer 0 (even total step count).
    if (lane < NC) {
        const int c = lane;
        float wl[H];
#pragma unroll
        for (int k = 0; k < H; k++) wl[k] = W_lin[c * H + k];
        const float bl = b_lin[c];
#pragma unroll
        for (int e = 0; e < EPW; e++) {
            const float* hE = &h_sh[w][0][e][0];
            float sE = bl;
#pragma unroll
            for (int k = 0; k < H; k++) sE = fmaf(wl[k], hE[k], sE);
            out[(size_t)(b0 + e) * NC + c] = sE;
        }
    }
}

extern "C" void kernel_launch(void* const* d_in, const int* in_sizes, int n_in,
                              void* d_out, int out_size) {
    const float* inputs = (const float*)d_in[0];
    const float* W_ih   = (const float*)d_in[1];
    const float* W_hh   = (const float*)d_in[2];
    const float* b_mod  = (const float*)d_in[3];
    const float* W_lin  = (const float*)d_in[4];
    const float* b_lin  = (const float*)d_in[5];
    float* out = (float*)d_out;

    const int nblocks = BATCHN / (EPW * WARPS);   // 2048
    rnn_modrelu_kernel<<<nblocks, THREADS>>>(inputs, W_ih, W_hh, b_mod,
                                             W_lin, b_lin, out);
}